// round 2
// baseline (speedup 1.0000x reference)
#include <cuda_runtime.h>
#include <cstdint>

// ---------------------------------------------------------------------------
// SubGraph: 3x (MLP -> gather/scatter-max -> concat) -> cluster max-pool ->
// column-wise L2 normalization.
// N=50000, E=800000, C0=64, H=64, NC=2500. Channels 64->128->256->512.
// NOTE: edge_index / cluster are int32 on device (JAX x64 disabled).
// ---------------------------------------------------------------------------

#define NINF_ENC 0x007FFFFFu   // order-preserving encoding of -inf

__device__ __forceinline__ unsigned fenc(float f) {
    unsigned b = __float_as_uint(f);
    return (b & 0x80000000u) ? ~b : (b | 0x80000000u);
}
// decode; non-finite (i.e. the -inf init of empty segments) -> 0
__device__ __forceinline__ float fdec0(unsigned e) {
    unsigned b = (e & 0x80000000u) ? (e & 0x7FFFFFFFu) : ~e;
    if ((b & 0x7F800000u) == 0x7F800000u) return 0.0f;
    return __uint_as_float(b);
}

// Static scratch (no allocations allowed); force 16B alignment for float4 paths
__device__ __align__(16) float    g_X1[50000 * 128];
__device__ __align__(16) float    g_X2[50000 * 256];
__device__ __align__(16) float    g_X3[50000 * 512];
__device__ __align__(16) unsigned g_pool[2500 * 512];

// ---------------------------------------------------------------------------
// Fused MLP: Y[:, :C] = relu(X@w1+b1)@w2 + b2 ;  Y[:, C:2C] = enc(-inf)
// X: [n, C] row-major; Y: [n, 2C] row-major.
// Block: 256 threads, 64-row tile. 16x16 thread grid, 4x4 microtile.
// ---------------------------------------------------------------------------
template<int C>
__global__ void __launch_bounds__(256) mlp_kernel(
    const float* __restrict__ X,
    const float* __restrict__ w1, const float* __restrict__ b1,
    const float* __restrict__ w2, const float* __restrict__ b2,
    float* __restrict__ Y, int n)
{
    constexpr int LD  = 2 * C;
    constexpr int V   = C / 4;      // float4 per input row
    constexpr int TSL = 68;         // padded t stride

    extern __shared__ float sm[];
    float* xs = sm;                 // [C][64]  transposed: xs[k*64 + r]
    float* ws = xs + C * 64;        // w1 [C][64] then w2 [64][C]
    float* ts = ws + C * 64;        // t  [64][68] row-major
    float* bs = ts + 64 * TSL;      // b1 (64) then b2 (C)

    const int tid = threadIdx.x;
    const int tx = tid & 15, ty = tid >> 4;
    const int r0 = ty * 4, j0 = tx * 4;
    const int rowBase = blockIdx.x * 64;

    // load X tile transposed (conflict-free stores; lanes -> consecutive rows)
    for (int i = tid; i < 64 * V; i += 256) {
        int r  = i & 63;
        int kv = i >> 6;
        int row = rowBase + r;
        float4 v = make_float4(0.f, 0.f, 0.f, 0.f);
        if (row < n) v = *(const float4*)&X[(long)row * C + kv * 4];
        xs[(kv * 4 + 0) * 64 + r] = v.x;
        xs[(kv * 4 + 1) * 64 + r] = v.y;
        xs[(kv * 4 + 2) * 64 + r] = v.z;
        xs[(kv * 4 + 3) * 64 + r] = v.w;
    }
    // load w1, b1
    for (int i = tid; i < C * 16; i += 256)
        ((float4*)ws)[i] = ((const float4*)w1)[i];
    if (tid < 64) bs[tid] = b1[tid];
    __syncthreads();

    // ---- matmul1: t[64][64] = X_tile @ w1 ----
    float acc[4][4] = {};
#pragma unroll 4
    for (int k = 0; k < C; ++k) {
        float4 xv = *(const float4*)(xs + k * 64 + r0);
        float4 wv = *(const float4*)(ws + k * 64 + j0);
        float xr[4] = {xv.x, xv.y, xv.z, xv.w};
        float wr[4] = {wv.x, wv.y, wv.z, wv.w};
#pragma unroll
        for (int i = 0; i < 4; ++i)
#pragma unroll
            for (int j = 0; j < 4; ++j)
                acc[i][j] += xr[i] * wr[j];
    }
    // relu + b1, store t
#pragma unroll
    for (int i = 0; i < 4; ++i) {
        float4 o;
        o.x = fmaxf(acc[i][0] + bs[j0 + 0], 0.f);
        o.y = fmaxf(acc[i][1] + bs[j0 + 1], 0.f);
        o.z = fmaxf(acc[i][2] + bs[j0 + 2], 0.f);
        o.w = fmaxf(acc[i][3] + bs[j0 + 3], 0.f);
        *(float4*)&ts[(r0 + i) * TSL + j0] = o;
    }
    __syncthreads();

    // load w2, b2 (reuse ws)
    for (int i = tid; i < C * 16; i += 256)
        ((float4*)ws)[i] = ((const float4*)w2)[i];
    for (int i = tid; i < C; i += 256) bs[64 + i] = b2[i];
    __syncthreads();

    // ---- matmul2: h[64][C] = t @ w2 (+b2) ; write out + aggr init ----
    const float* bs2 = bs + 64;
#pragma unroll
    for (int cc = 0; cc < C / 64; ++cc) {
        float a2[4][4] = {};
#pragma unroll 4
        for (int k = 0; k < 64; ++k) {
            float t0 = ts[(r0 + 0) * TSL + k];
            float t1 = ts[(r0 + 1) * TSL + k];
            float t2 = ts[(r0 + 2) * TSL + k];
            float t3 = ts[(r0 + 3) * TSL + k];
            float4 wv = *(const float4*)(ws + k * C + cc * 64 + j0);
            a2[0][0] += t0 * wv.x; a2[0][1] += t0 * wv.y; a2[0][2] += t0 * wv.z; a2[0][3] += t0 * wv.w;
            a2[1][0] += t1 * wv.x; a2[1][1] += t1 * wv.y; a2[1][2] += t1 * wv.z; a2[1][3] += t1 * wv.w;
            a2[2][0] += t2 * wv.x; a2[2][1] += t2 * wv.y; a2[2][2] += t2 * wv.z; a2[2][3] += t2 * wv.w;
            a2[3][0] += t3 * wv.x; a2[3][1] += t3 * wv.y; a2[3][2] += t3 * wv.z; a2[3][3] += t3 * wv.w;
        }
        int col = cc * 64 + j0;
        float4 bb = *(const float4*)&bs2[col];
        uint4 ninf = make_uint4(NINF_ENC, NINF_ENC, NINF_ENC, NINF_ENC);
#pragma unroll
        for (int i = 0; i < 4; ++i) {
            int row = rowBase + r0 + i;
            if (row < n) {
                float4 o;
                o.x = a2[i][0] + bb.x;
                o.y = a2[i][1] + bb.y;
                o.z = a2[i][2] + bb.z;
                o.w = a2[i][3] + bb.w;
                *(float4*)&Y[(long)row * LD + col] = o;
                *(uint4*)((unsigned*)Y + (long)row * LD + C + col) = ninf;
            }
        }
    }
}

// ---------------------------------------------------------------------------
// Edge scatter-max: for each edge e, aggr[dst] = max(aggr[dst], h[src])
// h rows are Xn[:, :C], encoded aggr is Xn[:, C:2C]. One warp -> EPW edges.
// ---------------------------------------------------------------------------
template<int C>
__global__ void __launch_bounds__(256) scatter_max_kernel(
    float* __restrict__ Xn,
    const int* __restrict__ src, const int* __restrict__ dst, int E)
{
    constexpr int LD  = 2 * C;
    constexpr int V   = C / 4;
    constexpr int LPE = (V < 32) ? V : 32;
    constexpr int EPW = 32 / LPE;

    int gwarp = (int)((blockIdx.x * 256u + threadIdx.x) >> 5);
    int lane  = threadIdx.x & 31;
    long e = (long)gwarp * EPW + (EPW > 1 ? lane / LPE : 0);
    if (e >= E) return;
    int li = lane % LPE;

    int s = src[e];
    int d = dst[e];
    const float4* hp = (const float4*)(Xn + (long)s * LD);
    unsigned* ap = (unsigned*)Xn + (long)d * LD + C;

    for (int v = li; v < V; v += LPE) {
        float4 h = hp[v];
        unsigned* a = ap + v * 4;
        unsigned e0 = fenc(h.x), e1 = fenc(h.y), e2 = fenc(h.z), e3 = fenc(h.w);
        // monotonic values -> a stale read can only be <= current -> safe skip
        if (e0 > a[0]) atomicMax(a + 0, e0);
        if (e1 > a[1]) atomicMax(a + 1, e1);
        if (e2 > a[2]) atomicMax(a + 2, e2);
        if (e3 > a[3]) atomicMax(a + 3, e3);
    }
}

// Decode aggr half in place: encoded unsigned -> float, empty segments -> 0
template<int C>
__global__ void decode_kernel(float* __restrict__ Xn, int n)
{
    constexpr int V = C / 4;
    int total = n * V;
    int i = blockIdx.x * blockDim.x + threadIdx.x;
    if (i >= total) return;
    int row = i / V, v = i % V;
    unsigned* p = (unsigned*)Xn + (long)row * (2 * C) + C + v * 4;
    uint4 u = *(uint4*)p;
    float4 f;
    f.x = fdec0(u.x); f.y = fdec0(u.y); f.z = fdec0(u.z); f.w = fdec0(u.w);
    *(float4*)p = f;
}

__global__ void init_pool_kernel(unsigned* __restrict__ pool, int total)
{
    int i = blockIdx.x * blockDim.x + threadIdx.x;
    if (i < total) pool[i] = NINF_ENC;
}

// Cluster max-pool: one warp per node, 512 channels
__global__ void __launch_bounds__(256) pool_kernel(
    const float* __restrict__ X3, const int* __restrict__ cl,
    unsigned* __restrict__ pool, int n)
{
    int node = (int)((blockIdx.x * 256u + threadIdx.x) >> 5);
    int lane = threadIdx.x & 31;
    if (node >= n) return;
    int c = cl[node];
    const float4* xp = (const float4*)(X3 + (long)node * 512);
    unsigned* pp = pool + (long)c * 512;
    for (int v = lane; v < 128; v += 32) {
        float4 h = xp[v];
        unsigned* a = pp + v * 4;
        unsigned e0 = fenc(h.x), e1 = fenc(h.y), e2 = fenc(h.z), e3 = fenc(h.w);
        if (e0 > a[0]) atomicMax(a + 0, e0);
        if (e1 > a[1]) atomicMax(a + 1, e1);
        if (e2 > a[2]) atomicMax(a + 2, e2);
        if (e3 > a[3]) atomicMax(a + 3, e3);
    }
}

// Column-wise normalize: out[r][col] = pooled[r][col] / (||pooled[:,col]|| + 1e-6)
__global__ void __launch_bounds__(256) normalize_kernel(
    const unsigned* __restrict__ pool, float* __restrict__ out, int nc)
{
    int col = blockIdx.x;   // 512 blocks
    float ss = 0.f;
    for (int r = threadIdx.x; r < nc; r += blockDim.x) {
        float v = fdec0(pool[(long)r * 512 + col]);
        ss += v * v;
    }
    __shared__ float red[256];
    red[threadIdx.x] = ss;
    __syncthreads();
    for (int s = 128; s > 0; s >>= 1) {
        if (threadIdx.x < s) red[threadIdx.x] += red[threadIdx.x + s];
        __syncthreads();
    }
    float inv = 1.0f / (sqrtf(red[0]) + 1e-6f);
    for (int r = threadIdx.x; r < nc; r += blockDim.x) {
        float v = fdec0(pool[(long)r * 512 + col]);
        out[(long)r * 512 + col] = v * inv;
    }
}

// ---------------------------------------------------------------------------
static int mlp_smem(int C) { return (2 * C * 64 + 64 * 68 + 64 + C) * 4; }

extern "C" void kernel_launch(void* const* d_in, const int* in_sizes, int n_in,
                              void* d_out, int out_size)
{
    const float* x   = (const float*)d_in[0];
    const int*   ei  = (const int*)d_in[1];   // int32 (JAX x64 disabled)
    const int*   cl  = (const int*)d_in[2];   // int32
    const float *w1_0 = (const float*)d_in[3],  *b1_0 = (const float*)d_in[4];
    const float *w2_0 = (const float*)d_in[5],  *b2_0 = (const float*)d_in[6];
    const float *w1_1 = (const float*)d_in[7],  *b1_1 = (const float*)d_in[8];
    const float *w2_1 = (const float*)d_in[9],  *b2_1 = (const float*)d_in[10];
    const float *w1_2 = (const float*)d_in[11], *b1_2 = (const float*)d_in[12];
    const float *w2_2 = (const float*)d_in[13], *b2_2 = (const float*)d_in[14];

    int n  = in_sizes[0] / 64;
    int E  = in_sizes[1] / 2;
    int nc = out_size / 512;
    const int* src = ei;
    const int* dst = ei + E;

    float* X1; cudaGetSymbolAddress((void**)&X1, g_X1);
    float* X2; cudaGetSymbolAddress((void**)&X2, g_X2);
    float* X3; cudaGetSymbolAddress((void**)&X3, g_X3);
    unsigned* pool; cudaGetSymbolAddress((void**)&pool, g_pool);

    cudaFuncSetAttribute(mlp_kernel<64>,  cudaFuncAttributeMaxDynamicSharedMemorySize, mlp_smem(64));
    cudaFuncSetAttribute(mlp_kernel<128>, cudaFuncAttributeMaxDynamicSharedMemorySize, mlp_smem(128));
    cudaFuncSetAttribute(mlp_kernel<256>, cudaFuncAttributeMaxDynamicSharedMemorySize, mlp_smem(256));

    int nb = (n + 63) / 64;

    // ---- Layer 0: C=64 ----
    mlp_kernel<64><<<nb, 256, mlp_smem(64)>>>(x, w1_0, b1_0, w2_0, b2_0, X1, n);
    {
        int nwarp = (E + 1) / 2;                 // 2 edges per warp
        scatter_max_kernel<64><<<(nwarp + 7) / 8, 256>>>(X1, src, dst, E);
    }
    decode_kernel<64><<<(n * 16 + 255) / 256, 256>>>(X1, n);

    // ---- Layer 1: C=128 ----
    mlp_kernel<128><<<nb, 256, mlp_smem(128)>>>(X1, w1_1, b1_1, w2_1, b2_1, X2, n);
    scatter_max_kernel<128><<<(E + 7) / 8, 256>>>(X2, src, dst, E);
    decode_kernel<128><<<(n * 32 + 255) / 256, 256>>>(X2, n);

    // ---- Layer 2: C=256 ----
    mlp_kernel<256><<<nb, 256, mlp_smem(256)>>>(X2, w1_2, b1_2, w2_2, b2_2, X3, n);
    scatter_max_kernel<256><<<(E + 7) / 8, 256>>>(X3, src, dst, E);
    decode_kernel<256><<<(n * 64 + 255) / 256, 256>>>(X3, n);

    // ---- Cluster pool + normalize ----
    init_pool_kernel<<<(nc * 512 + 255) / 256, 256>>>(pool, nc * 512);
    pool_kernel<<<(n + 7) / 8, 256>>>(X3, cl, pool, n);
    normalize_kernel<<<512, 256>>>(pool, (float*)d_out, nc);
}

// round 3
// speedup vs baseline: 2.5350x; 2.5350x over previous
#include <cuda_runtime.h>
#include <cstdint>

// ---------------------------------------------------------------------------
// SubGraph: 3x (MLP -> gather/scatter-max -> concat) -> cluster max-pool ->
// column-wise L2 normalization.
// N=50000, E=800000, C0=64, H=64, NC=2500. Channels 64->128->256->512.
// Round 3: CSR-based aggregation (no atomics), chunked-K MLP, CSR pool.
// ---------------------------------------------------------------------------

// Static scratch (no allocations allowed)
__device__ __align__(16) float g_X1[50000 * 128];
__device__ __align__(16) float g_X2[50000 * 256];
__device__ __align__(16) float g_X3[50000 * 512];
__device__ __align__(16) float g_pool[2500 * 512];

__device__ int g_cnt[50000];
__device__ int g_off[50001];
__device__ int g_cur[50000];
__device__ int g_csr[800000];

__device__ int g_ccnt[2500];
__device__ int g_coff[2501];
__device__ int g_ccur[2500];
__device__ int g_ccsr[50000];

__device__ __forceinline__ float4 max4(float4 a, float4 b) {
    return make_float4(fmaxf(a.x, b.x), fmaxf(a.y, b.y),
                       fmaxf(a.z, b.z), fmaxf(a.w, b.w));
}

// ---------------------------------------------------------------------------
// CSR build
// ---------------------------------------------------------------------------
__global__ void hist_kernel(const int* __restrict__ idx, int* __restrict__ cnt, int m)
{
    int i = blockIdx.x * blockDim.x + threadIdx.x;
    if (i < m) atomicAdd(&cnt[idx[i]], 1);
}

// single-block exclusive scan (n <= ~1M fine); writes off[0..n], cur[0..n-1]
__global__ void scan_kernel(const int* __restrict__ cnt, int* __restrict__ off,
                            int* __restrict__ cur, int n)
{
    __shared__ int sums[1024];
    int tid = threadIdx.x;
    int chunk = (n + 1023) >> 10;
    int start = tid * chunk;
    int lim = min(start + chunk, n);
    int s = 0;
    for (int i = start; i < lim; ++i) s += cnt[i];
    sums[tid] = s;
    __syncthreads();
    for (int d = 1; d < 1024; d <<= 1) {
        int v = (tid >= d) ? sums[tid - d] : 0;
        __syncthreads();
        sums[tid] += v;
        __syncthreads();
    }
    int run = (tid == 0) ? 0 : sums[tid - 1];
    for (int i = start; i < lim; ++i) {
        off[i] = run; cur[i] = run;
        run += cnt[i];
    }
    if (tid == 1023) off[n] = sums[1023];
}

__global__ void fill_edge_kernel(const int* __restrict__ src, const int* __restrict__ dst,
                                 int* __restrict__ cur, int* __restrict__ csr, int E)
{
    int e = blockIdx.x * blockDim.x + threadIdx.x;
    if (e >= E) return;
    int pos = atomicAdd(&cur[dst[e]], 1);
    csr[pos] = src[e];
}

__global__ void fill_node_kernel(const int* __restrict__ cl, int* __restrict__ ccur,
                                 int* __restrict__ ccsr, int n)
{
    int i = blockIdx.x * blockDim.x + threadIdx.x;
    if (i >= n) return;
    int pos = atomicAdd(&ccur[cl[i]], 1);
    ccsr[pos] = i;
}

// ---------------------------------------------------------------------------
// Fused MLP: Y[:, :C] = relu(X@w1+b1)@w2 + b2   (aggr half written by agg)
// K-chunked matmul1 (KC=128), t-buffer aliases xs, w2/biases via L1 (__ldg).
// Block: 256 threads, 64-row tile, 16x16 thread grid, 4x4 microtile.
// ---------------------------------------------------------------------------
template<int C>
__global__ void __launch_bounds__(256) mlp_kernel(
    const float* __restrict__ X,
    const float* __restrict__ w1, const float* __restrict__ b1,
    const float* __restrict__ w2, const float* __restrict__ b2,
    float* __restrict__ Y, int n)
{
    constexpr int LD  = 2 * C;
    constexpr int KC  = (C < 128) ? C : 128;   // K chunk
    constexpr int NCH = C / KC;
    constexpr int TSL = 68;

    extern __shared__ float sm[];
    float* ws = sm;                 // w1 chunk [KC][64]
    float* xs = ws + KC * 64;       // x chunk transposed [KC][64]; aliased by ts
    float* ts = xs;                 // t [64][68] (reuses xs region)

    const int tid = threadIdx.x;
    const int tx = tid & 15, ty = tid >> 4;
    const int r0 = ty * 4, j0 = tx * 4;
    const int rowBase = blockIdx.x * 64;

    float acc[4][4] = {};
#pragma unroll
    for (int kc = 0; kc < NCH; ++kc) {
        // load X chunk transposed: xs[k*64 + r]
        for (int i = tid; i < 64 * (KC / 4); i += 256) {
            int r  = i & 63;
            int kv = i >> 6;
            int row = rowBase + r;
            float4 v = make_float4(0.f, 0.f, 0.f, 0.f);
            if (row < n) v = *(const float4*)&X[(long)row * C + kc * KC + kv * 4];
            xs[(kv * 4 + 0) * 64 + r] = v.x;
            xs[(kv * 4 + 1) * 64 + r] = v.y;
            xs[(kv * 4 + 2) * 64 + r] = v.z;
            xs[(kv * 4 + 3) * 64 + r] = v.w;
        }
        // load w1 chunk [KC][64]
        const float4* w1c = (const float4*)(w1 + (long)kc * KC * 64);
        for (int i = tid; i < KC * 16; i += 256)
            ((float4*)ws)[i] = w1c[i];
        __syncthreads();

#pragma unroll 4
        for (int k = 0; k < KC; ++k) {
            float4 xv = *(const float4*)(xs + k * 64 + r0);
            float4 wv = *(const float4*)(ws + k * 64 + j0);
            float xr[4] = {xv.x, xv.y, xv.z, xv.w};
            float wr[4] = {wv.x, wv.y, wv.z, wv.w};
#pragma unroll
            for (int i = 0; i < 4; ++i)
#pragma unroll
                for (int j = 0; j < 4; ++j)
                    acc[i][j] += xr[i] * wr[j];
        }
        __syncthreads();
    }

    // relu + b1 -> ts (aliased into xs region; safe after trailing sync)
    float4 bb1 = __ldg((const float4*)&b1[j0]);
    float bb1a[4] = {bb1.x, bb1.y, bb1.z, bb1.w};
#pragma unroll
    for (int i = 0; i < 4; ++i) {
        float4 o;
        o.x = fmaxf(acc[i][0] + bb1a[0], 0.f);
        o.y = fmaxf(acc[i][1] + bb1a[1], 0.f);
        o.z = fmaxf(acc[i][2] + bb1a[2], 0.f);
        o.w = fmaxf(acc[i][3] + bb1a[3], 0.f);
        *(float4*)&ts[(r0 + i) * TSL + j0] = o;
    }
    __syncthreads();

    // matmul2: h[64][C] = t @ w2 (+b2); w2 via L1
#pragma unroll
    for (int cc = 0; cc < C / 64; ++cc) {
        float a2[4][4] = {};
#pragma unroll 4
        for (int k = 0; k < 64; ++k) {
            float t0 = ts[(r0 + 0) * TSL + k];
            float t1 = ts[(r0 + 1) * TSL + k];
            float t2 = ts[(r0 + 2) * TSL + k];
            float t3 = ts[(r0 + 3) * TSL + k];
            float4 wv = __ldg((const float4*)&w2[(long)k * C + cc * 64 + j0]);
            a2[0][0] += t0 * wv.x; a2[0][1] += t0 * wv.y; a2[0][2] += t0 * wv.z; a2[0][3] += t0 * wv.w;
            a2[1][0] += t1 * wv.x; a2[1][1] += t1 * wv.y; a2[1][2] += t1 * wv.z; a2[1][3] += t1 * wv.w;
            a2[2][0] += t2 * wv.x; a2[2][1] += t2 * wv.y; a2[2][2] += t2 * wv.z; a2[2][3] += t2 * wv.w;
            a2[3][0] += t3 * wv.x; a2[3][1] += t3 * wv.y; a2[3][2] += t3 * wv.z; a2[3][3] += t3 * wv.w;
        }
        int col = cc * 64 + j0;
        float4 bb = __ldg((const float4*)&b2[col]);
#pragma unroll
        for (int i = 0; i < 4; ++i) {
            int row = rowBase + r0 + i;
            if (row < n) {
                float4 o;
                o.x = a2[i][0] + bb.x;
                o.y = a2[i][1] + bb.y;
                o.z = a2[i][2] + bb.z;
                o.w = a2[i][3] + bb.w;
                *(float4*)&Y[(long)row * LD + col] = o;
            }
        }
    }
}

// ---------------------------------------------------------------------------
// CSR gather-max aggregation: aggr[node] = max over in-edges of h[src]; 0 if none.
// h rows are Xn[:, :C]; aggr written to Xn[:, C:2C] as float. Warp(-part) per node.
// ---------------------------------------------------------------------------
template<int C>
__global__ void __launch_bounds__(256) agg_kernel(
    float* __restrict__ Xn,
    const int* __restrict__ csr, const int* __restrict__ off, int n)
{
    constexpr int LD  = 2 * C;
    constexpr int V   = C / 4;
    constexpr int LPE = (V < 32) ? V : 32;   // lanes per node
    constexpr int EPW = 32 / LPE;            // nodes per warp
    constexpr int NV  = V / LPE;             // float4 per lane

    int gwarp = (int)((blockIdx.x * 256u + threadIdx.x) >> 5);
    int lane  = threadIdx.x & 31;
    int node  = gwarp * EPW + (EPW > 1 ? lane / LPE : 0);
    if (node >= n) return;
    int li = lane % LPE;

    int beg = off[node], end = off[node + 1];

    float4 m[NV];
#pragma unroll
    for (int v = 0; v < NV; ++v)
        m[v] = make_float4(-INFINITY, -INFINITY, -INFINITY, -INFINITY);

    int e = beg;
    for (; e + 1 < end; e += 2) {
        int s0 = csr[e], s1 = csr[e + 1];
        const float4* h0 = (const float4*)(Xn + (long)s0 * LD);
        const float4* h1 = (const float4*)(Xn + (long)s1 * LD);
#pragma unroll
        for (int v = 0; v < NV; ++v) {
            float4 a = h0[li + v * LPE];
            float4 b = h1[li + v * LPE];
            m[v] = max4(m[v], max4(a, b));
        }
    }
    if (e < end) {
        const float4* h0 = (const float4*)(Xn + (long)csr[e] * LD);
#pragma unroll
        for (int v = 0; v < NV; ++v)
            m[v] = max4(m[v], h0[li + v * LPE]);
    }

    float4* ap = (float4*)(Xn + (long)node * LD + C);
    if (beg == end) {
#pragma unroll
        for (int v = 0; v < NV; ++v)
            ap[li + v * LPE] = make_float4(0.f, 0.f, 0.f, 0.f);
    } else {
#pragma unroll
        for (int v = 0; v < NV; ++v)
            ap[li + v * LPE] = m[v];
    }
}

// ---------------------------------------------------------------------------
// Cluster max-pool via CSR: one 128-thread block per cluster, float4 per thread.
// ---------------------------------------------------------------------------
__global__ void __launch_bounds__(128) pool_kernel(
    const float* __restrict__ X3, const int* __restrict__ ccsr,
    const int* __restrict__ coff, float* __restrict__ pool)
{
    int c = blockIdx.x;
    int t = threadIdx.x;       // float4 index 0..127 (512 channels)
    int beg = coff[c], end = coff[c + 1];

    float4 m = make_float4(-INFINITY, -INFINITY, -INFINITY, -INFINITY);
    int i = beg;
    for (; i + 1 < end; i += 2) {
        float4 a = ((const float4*)(X3 + (long)ccsr[i] * 512))[t];
        float4 b = ((const float4*)(X3 + (long)ccsr[i + 1] * 512))[t];
        m = max4(m, max4(a, b));
    }
    if (i < end)
        m = max4(m, ((const float4*)(X3 + (long)ccsr[i] * 512))[t]);
    if (beg == end) m = make_float4(0.f, 0.f, 0.f, 0.f);
    ((float4*)(pool + (long)c * 512))[t] = m;
}

// Column-wise normalize: out[r][col] = pool[r][col] / (||pool[:,col]|| + 1e-6)
__global__ void __launch_bounds__(256) normalize_kernel(
    const float* __restrict__ pool, float* __restrict__ out, int nc)
{
    int col = blockIdx.x;   // 512 blocks
    float ss = 0.f;
    for (int r = threadIdx.x; r < nc; r += blockDim.x) {
        float v = pool[(long)r * 512 + col];
        ss += v * v;
    }
    __shared__ float red[256];
    red[threadIdx.x] = ss;
    __syncthreads();
    for (int s = 128; s > 0; s >>= 1) {
        if (threadIdx.x < s) red[threadIdx.x] += red[threadIdx.x + s];
        __syncthreads();
    }
    float inv = 1.0f / (sqrtf(red[0]) + 1e-6f);
    for (int r = threadIdx.x; r < nc; r += blockDim.x)
        out[(long)r * 512 + col] = pool[(long)r * 512 + col] * inv;
}

// ---------------------------------------------------------------------------
static int mlp_smem(int C) {
    int KC = (C < 128) ? C : 128;
    int ts = 64 * 68;
    int xs = KC * 64;
    int buf = (ts > xs) ? ts : xs;
    return (KC * 64 + buf) * 4;
}

extern "C" void kernel_launch(void* const* d_in, const int* in_sizes, int n_in,
                              void* d_out, int out_size)
{
    const float* x   = (const float*)d_in[0];
    const int*   ei  = (const int*)d_in[1];   // int32 (JAX x64 disabled)
    const int*   cl  = (const int*)d_in[2];   // int32
    const float *w1_0 = (const float*)d_in[3],  *b1_0 = (const float*)d_in[4];
    const float *w2_0 = (const float*)d_in[5],  *b2_0 = (const float*)d_in[6];
    const float *w1_1 = (const float*)d_in[7],  *b1_1 = (const float*)d_in[8];
    const float *w2_1 = (const float*)d_in[9],  *b2_1 = (const float*)d_in[10];
    const float *w1_2 = (const float*)d_in[11], *b1_2 = (const float*)d_in[12];
    const float *w2_2 = (const float*)d_in[13], *b2_2 = (const float*)d_in[14];

    int n  = in_sizes[0] / 64;
    int E  = in_sizes[1] / 2;
    int nc = out_size / 512;
    const int* src = ei;
    const int* dst = ei + E;

    float* X1;   cudaGetSymbolAddress((void**)&X1, g_X1);
    float* X2;   cudaGetSymbolAddress((void**)&X2, g_X2);
    float* X3;   cudaGetSymbolAddress((void**)&X3, g_X3);
    float* pool; cudaGetSymbolAddress((void**)&pool, g_pool);
    int *cnt, *off, *cur, *csr, *ccnt, *coff, *ccur, *ccsr;
    cudaGetSymbolAddress((void**)&cnt,  g_cnt);
    cudaGetSymbolAddress((void**)&off,  g_off);
    cudaGetSymbolAddress((void**)&cur,  g_cur);
    cudaGetSymbolAddress((void**)&csr,  g_csr);
    cudaGetSymbolAddress((void**)&ccnt, g_ccnt);
    cudaGetSymbolAddress((void**)&coff, g_coff);
    cudaGetSymbolAddress((void**)&ccur, g_ccur);
    cudaGetSymbolAddress((void**)&ccsr, g_ccsr);

    cudaFuncSetAttribute(mlp_kernel<64>,  cudaFuncAttributeMaxDynamicSharedMemorySize, mlp_smem(64));
    cudaFuncSetAttribute(mlp_kernel<128>, cudaFuncAttributeMaxDynamicSharedMemorySize, mlp_smem(128));
    cudaFuncSetAttribute(mlp_kernel<256>, cudaFuncAttributeMaxDynamicSharedMemorySize, mlp_smem(256));

    // ---- CSR build (edges by dst, nodes by cluster) ----
    cudaMemsetAsync(cnt,  0, (size_t)n  * sizeof(int));
    cudaMemsetAsync(ccnt, 0, (size_t)nc * sizeof(int));
    hist_kernel<<<(E + 255) / 256, 256>>>(dst, cnt, E);
    hist_kernel<<<(n + 255) / 256, 256>>>(cl, ccnt, n);
    scan_kernel<<<1, 1024>>>(cnt, off, cur, n);
    scan_kernel<<<1, 1024>>>(ccnt, coff, ccur, nc);
    fill_edge_kernel<<<(E + 255) / 256, 256>>>(src, dst, cur, csr, E);
    fill_node_kernel<<<(n + 255) / 256, 256>>>(cl, ccur, ccsr, n);

    int nb = (n + 63) / 64;

    // ---- Layer 0: C=64 ----
    mlp_kernel<64><<<nb, 256, mlp_smem(64)>>>(x, w1_0, b1_0, w2_0, b2_0, X1, n);
    agg_kernel<64><<<((n + 1) / 2 * 32 + 255) / 256, 256>>>(X1, csr, off, n);

    // ---- Layer 1: C=128 ----
    mlp_kernel<128><<<nb, 256, mlp_smem(128)>>>(X1, w1_1, b1_1, w2_1, b2_1, X2, n);
    agg_kernel<128><<<(n * 32 + 255) / 256, 256>>>(X2, csr, off, n);

    // ---- Layer 2: C=256 ----
    mlp_kernel<256><<<nb, 256, mlp_smem(256)>>>(X2, w1_2, b1_2, w2_2, b2_2, X3, n);
    agg_kernel<256><<<(n * 32 + 255) / 256, 256>>>(X3, csr, off, n);

    // ---- Cluster pool + normalize ----
    pool_kernel<<<nc, 128>>>(X3, ccsr, coff, pool);
    normalize_kernel<<<512, 256>>>(pool, (float*)d_out, nc);
}

// round 4
// speedup vs baseline: 2.7473x; 1.0838x over previous
#include <cuda_runtime.h>
#include <cstdint>

// ---------------------------------------------------------------------------
// SubGraph: 3x (MLP -> gather/scatter-max -> concat) -> cluster max-pool ->
// column-wise L2 normalization.
// N=50000, E=800000, C0=64, H=64, NC=2500. Channels 64->128->256->512.
// Round 4: higher-occupancy MLP (static 33KB smem, w2 staged, k4 inner),
//          CSR build overlapped on a second stream, coalesced normalize.
// ---------------------------------------------------------------------------

// Static scratch (no allocations allowed)
__device__ __align__(16) float g_X1[50000 * 128];
__device__ __align__(16) float g_X2[50000 * 256];
__device__ __align__(16) float g_X3[50000 * 512];
__device__ __align__(16) float g_pool[2500 * 512];

__device__ int g_cnt[50000];
__device__ int g_off[50001];
__device__ int g_cur[50000];
__device__ int g_csr[800000];

__device__ int g_ccnt[2500];
__device__ int g_coff[2501];
__device__ int g_ccur[2500];
__device__ int g_ccsr[50000];

__device__ __forceinline__ float4 max4(float4 a, float4 b) {
    return make_float4(fmaxf(a.x, b.x), fmaxf(a.y, b.y),
                       fmaxf(a.z, b.z), fmaxf(a.w, b.w));
}

// ---------------------------------------------------------------------------
// CSR build
// ---------------------------------------------------------------------------
__global__ void hist_kernel(const int* __restrict__ idx, int* __restrict__ cnt, int m)
{
    int i = blockIdx.x * blockDim.x + threadIdx.x;
    if (i < m) atomicAdd(&cnt[idx[i]], 1);
}

// single-block exclusive scan; writes off[0..n], cur[0..n-1]
__global__ void scan_kernel(const int* __restrict__ cnt, int* __restrict__ off,
                            int* __restrict__ cur, int n)
{
    __shared__ int sums[1024];
    int tid = threadIdx.x;
    int chunk = (n + 1023) >> 10;
    int start = tid * chunk;
    int lim = min(start + chunk, n);
    int s = 0;
    for (int i = start; i < lim; ++i) s += cnt[i];
    sums[tid] = s;
    __syncthreads();
    for (int d = 1; d < 1024; d <<= 1) {
        int v = (tid >= d) ? sums[tid - d] : 0;
        __syncthreads();
        sums[tid] += v;
        __syncthreads();
    }
    int run = (tid == 0) ? 0 : sums[tid - 1];
    for (int i = start; i < lim; ++i) {
        off[i] = run; cur[i] = run;
        run += cnt[i];
    }
    if (tid == 1023) off[n] = sums[1023];
}

__global__ void fill_edge_kernel(const int* __restrict__ src, const int* __restrict__ dst,
                                 int* __restrict__ cur, int* __restrict__ csr, int E)
{
    int e = blockIdx.x * blockDim.x + threadIdx.x;
    if (e >= E) return;
    int pos = atomicAdd(&cur[dst[e]], 1);
    csr[pos] = src[e];
}

__global__ void fill_node_kernel(const int* __restrict__ cl, int* __restrict__ ccur,
                                 int* __restrict__ ccsr, int n)
{
    int i = blockIdx.x * blockDim.x + threadIdx.x;
    if (i >= n) return;
    int pos = atomicAdd(&ccur[cl[i]], 1);
    ccsr[pos] = i;
}

// ---------------------------------------------------------------------------
// Fused MLP: Y[:, :C] = relu(X@w1+b1)@w2 + b2   (aggr half written by agg)
// KC=64 K-chunks; w1 chunk AND w2 output-slice staged in smem (ws).
// Static smem = 33KB -> 4 blocks/SM. 256 thr, 64-row tile, 4x4 microtile.
// ---------------------------------------------------------------------------
template<int C>
__global__ void __launch_bounds__(256, 4) mlp_kernel(
    const float* __restrict__ X,
    const float* __restrict__ w1, const float* __restrict__ b1,
    const float* __restrict__ w2, const float* __restrict__ b2,
    float* __restrict__ Y, int n)
{
    constexpr int LD  = 2 * C;
    constexpr int KC  = 64;
    constexpr int NCH = C / KC;
    constexpr int TSL = 68;

    __shared__ float ws[64 * 64];       // w1 chunk / w2 slice [64][64]
    __shared__ float buf[64 * TSL];     // xs [64][64] (chunk) aliased by ts [64][68]
    float* xs = buf;
    float* ts = buf;

    const int tid = threadIdx.x;
    const int tx = tid & 15, ty = tid >> 4;
    const int r0 = ty * 4, j0 = tx * 4;
    const int rowBase = blockIdx.x * 64;

    // ---- matmul1: t[64][64] = X_tile @ w1, K-chunked ----
    float acc[4][4] = {};
#pragma unroll
    for (int kc = 0; kc < NCH; ++kc) {
        for (int i = tid; i < 64 * 16; i += 256) {
            int r  = i & 63;
            int kv = i >> 6;
            int row = rowBase + r;
            float4 v = make_float4(0.f, 0.f, 0.f, 0.f);
            if (row < n) v = *(const float4*)&X[(long)row * C + kc * KC + kv * 4];
            xs[(kv * 4 + 0) * 64 + r] = v.x;
            xs[(kv * 4 + 1) * 64 + r] = v.y;
            xs[(kv * 4 + 2) * 64 + r] = v.z;
            xs[(kv * 4 + 3) * 64 + r] = v.w;
        }
        const float4* w1c = (const float4*)(w1 + (long)kc * KC * 64);
        for (int i = tid; i < KC * 16; i += 256)
            ((float4*)ws)[i] = w1c[i];
        __syncthreads();

#pragma unroll 4
        for (int k = 0; k < KC; ++k) {
            float4 xv = *(const float4*)(xs + k * 64 + r0);
            float4 wv = *(const float4*)(ws + k * 64 + j0);
            float xr[4] = {xv.x, xv.y, xv.z, xv.w};
            float wr[4] = {wv.x, wv.y, wv.z, wv.w};
#pragma unroll
            for (int i = 0; i < 4; ++i)
#pragma unroll
                for (int j = 0; j < 4; ++j)
                    acc[i][j] += xr[i] * wr[j];
        }
        __syncthreads();
    }

    // relu + b1 -> ts
    float4 bb1 = __ldg((const float4*)&b1[j0]);
    float bb1a[4] = {bb1.x, bb1.y, bb1.z, bb1.w};
#pragma unroll
    for (int i = 0; i < 4; ++i) {
        float4 o;
        o.x = fmaxf(acc[i][0] + bb1a[0], 0.f);
        o.y = fmaxf(acc[i][1] + bb1a[1], 0.f);
        o.z = fmaxf(acc[i][2] + bb1a[2], 0.f);
        o.w = fmaxf(acc[i][3] + bb1a[3], 0.f);
        *(float4*)&ts[(r0 + i) * TSL + j0] = o;
    }

    // ---- matmul2: h[64][C] = t @ w2 (+b2), 64-col output slices ----
#pragma unroll
    for (int cc = 0; cc < C / 64; ++cc) {
        __syncthreads();
        // stage w2 slice [64][64]: ws[k*64 + j] = w2[k*C + cc*64 + j]
        for (int i = tid; i < 64 * 16; i += 256) {
            int k = i >> 4, jv = i & 15;
            ((float4*)ws)[i] = __ldg((const float4*)&w2[(long)k * C + cc * 64 + jv * 4]);
        }
        __syncthreads();

        float a2[4][4] = {};
#pragma unroll
        for (int k4 = 0; k4 < 64; k4 += 4) {
            float4 t0 = *(const float4*)&ts[(r0 + 0) * TSL + k4];
            float4 t1 = *(const float4*)&ts[(r0 + 1) * TSL + k4];
            float4 t2 = *(const float4*)&ts[(r0 + 2) * TSL + k4];
            float4 t3 = *(const float4*)&ts[(r0 + 3) * TSL + k4];
            float4 w0 = *(const float4*)&ws[(k4 + 0) * 64 + j0];
            float4 w1v = *(const float4*)&ws[(k4 + 1) * 64 + j0];
            float4 w2v = *(const float4*)&ws[(k4 + 2) * 64 + j0];
            float4 w3 = *(const float4*)&ws[(k4 + 3) * 64 + j0];
            float tr[4][4] = {{t0.x, t0.y, t0.z, t0.w}, {t1.x, t1.y, t1.z, t1.w},
                              {t2.x, t2.y, t2.z, t2.w}, {t3.x, t3.y, t3.z, t3.w}};
            float wr[4][4] = {{w0.x, w0.y, w0.z, w0.w}, {w1v.x, w1v.y, w1v.z, w1v.w},
                              {w2v.x, w2v.y, w2v.z, w2v.w}, {w3.x, w3.y, w3.z, w3.w}};
#pragma unroll
            for (int kk = 0; kk < 4; ++kk)
#pragma unroll
                for (int i = 0; i < 4; ++i)
#pragma unroll
                    for (int j = 0; j < 4; ++j)
                        a2[i][j] += tr[i][kk] * wr[kk][j];
        }
        int col = cc * 64 + j0;
        float4 bb = __ldg((const float4*)&b2[col]);
#pragma unroll
        for (int i = 0; i < 4; ++i) {
            int row = rowBase + r0 + i;
            if (row < n) {
                float4 o;
                o.x = a2[i][0] + bb.x;
                o.y = a2[i][1] + bb.y;
                o.z = a2[i][2] + bb.z;
                o.w = a2[i][3] + bb.w;
                *(float4*)&Y[(long)row * LD + col] = o;
            }
        }
    }
}

// ---------------------------------------------------------------------------
// CSR gather-max aggregation: aggr[node] = max over in-edges of h[src]; 0 if none.
// 4-edge unrolled for MLP. Warp(-part) per node.
// ---------------------------------------------------------------------------
template<int C>
__global__ void __launch_bounds__(256) agg_kernel(
    float* __restrict__ Xn,
    const int* __restrict__ csr, const int* __restrict__ off, int n)
{
    constexpr int LD  = 2 * C;
    constexpr int V   = C / 4;
    constexpr int LPE = (V < 32) ? V : 32;   // lanes per node
    constexpr int EPW = 32 / LPE;            // nodes per warp
    constexpr int NV  = V / LPE;             // float4 per lane

    int gwarp = (int)((blockIdx.x * 256u + threadIdx.x) >> 5);
    int lane  = threadIdx.x & 31;
    int node  = gwarp * EPW + (EPW > 1 ? lane / LPE : 0);
    if (node >= n) return;
    int li = lane % LPE;

    int beg = off[node], end = off[node + 1];

    float4 m[NV];
#pragma unroll
    for (int v = 0; v < NV; ++v)
        m[v] = make_float4(-INFINITY, -INFINITY, -INFINITY, -INFINITY);

    int e = beg;
    for (; e + 3 < end; e += 4) {
        int s0 = __ldg(csr + e), s1 = __ldg(csr + e + 1);
        int s2 = __ldg(csr + e + 2), s3 = __ldg(csr + e + 3);
        const float4* h0 = (const float4*)(Xn + (long)s0 * LD);
        const float4* h1 = (const float4*)(Xn + (long)s1 * LD);
        const float4* h2 = (const float4*)(Xn + (long)s2 * LD);
        const float4* h3 = (const float4*)(Xn + (long)s3 * LD);
#pragma unroll
        for (int v = 0; v < NV; ++v) {
            float4 a = h0[li + v * LPE];
            float4 b = h1[li + v * LPE];
            float4 c = h2[li + v * LPE];
            float4 d = h3[li + v * LPE];
            m[v] = max4(m[v], max4(max4(a, b), max4(c, d)));
        }
    }
    for (; e < end; ++e) {
        const float4* h0 = (const float4*)(Xn + (long)__ldg(csr + e) * LD);
#pragma unroll
        for (int v = 0; v < NV; ++v)
            m[v] = max4(m[v], h0[li + v * LPE]);
    }

    float4* ap = (float4*)(Xn + (long)node * LD + C);
    if (beg == end) {
#pragma unroll
        for (int v = 0; v < NV; ++v)
            ap[li + v * LPE] = make_float4(0.f, 0.f, 0.f, 0.f);
    } else {
#pragma unroll
        for (int v = 0; v < NV; ++v)
            ap[li + v * LPE] = m[v];
    }
}

// ---------------------------------------------------------------------------
// Cluster max-pool via CSR: one 128-thread block per cluster, float4 per thread.
// ---------------------------------------------------------------------------
__global__ void __launch_bounds__(128) pool_kernel(
    const float* __restrict__ X3, const int* __restrict__ ccsr,
    const int* __restrict__ coff, float* __restrict__ pool)
{
    int c = blockIdx.x;
    int t = threadIdx.x;       // float4 index 0..127 (512 channels)
    int beg = coff[c], end = coff[c + 1];

    float4 m = make_float4(-INFINITY, -INFINITY, -INFINITY, -INFINITY);
    int i = beg;
    for (; i + 3 < end; i += 4) {
        float4 a = ((const float4*)(X3 + (long)ccsr[i] * 512))[t];
        float4 b = ((const float4*)(X3 + (long)ccsr[i + 1] * 512))[t];
        float4 c2 = ((const float4*)(X3 + (long)ccsr[i + 2] * 512))[t];
        float4 d = ((const float4*)(X3 + (long)ccsr[i + 3] * 512))[t];
        m = max4(m, max4(max4(a, b), max4(c2, d)));
    }
    for (; i < end; ++i)
        m = max4(m, ((const float4*)(X3 + (long)ccsr[i] * 512))[t]);
    if (beg == end) m = make_float4(0.f, 0.f, 0.f, 0.f);
    ((float4*)(pool + (long)c * 512))[t] = m;
}

// Column-wise normalize, coalesced: 16 blocks x 32 cols; 8 row-phases per col.
__global__ void __launch_bounds__(256) normalize_kernel(
    const float* __restrict__ pool, float* __restrict__ out, int nc)
{
    int lane  = threadIdx.x & 31;
    int phase = threadIdx.x >> 5;              // 0..7
    int col   = blockIdx.x * 32 + lane;

    float ss = 0.f;
    for (int r = phase; r < nc; r += 8) {
        float v = pool[(long)r * 512 + col];
        ss += v * v;
    }
    __shared__ float red[256];
    red[threadIdx.x] = ss;
    __syncthreads();
#pragma unroll
    for (int s = 128; s >= 32; s >>= 1) {
        if (threadIdx.x < s) red[threadIdx.x] += red[threadIdx.x + s];
        __syncthreads();
    }
    if (threadIdx.x < 32) red[threadIdx.x] = 1.0f / (sqrtf(red[threadIdx.x]) + 1e-6f);
    __syncthreads();
    float inv = red[lane];
    for (int r = phase; r < nc; r += 8)
        out[(long)r * 512 + col] = pool[(long)r * 512 + col] * inv;
}

// ---------------------------------------------------------------------------
extern "C" void kernel_launch(void* const* d_in, const int* in_sizes, int n_in,
                              void* d_out, int out_size)
{
    const float* x   = (const float*)d_in[0];
    const int*   ei  = (const int*)d_in[1];   // int32 (JAX x64 disabled)
    const int*   cl  = (const int*)d_in[2];   // int32
    const float *w1_0 = (const float*)d_in[3],  *b1_0 = (const float*)d_in[4];
    const float *w2_0 = (const float*)d_in[5],  *b2_0 = (const float*)d_in[6];
    const float *w1_1 = (const float*)d_in[7],  *b1_1 = (const float*)d_in[8];
    const float *w2_1 = (const float*)d_in[9],  *b2_1 = (const float*)d_in[10];
    const float *w1_2 = (const float*)d_in[11], *b1_2 = (const float*)d_in[12];
    const float *w2_2 = (const float*)d_in[13], *b2_2 = (const float*)d_in[14];

    int n  = in_sizes[0] / 64;
    int E  = in_sizes[1] / 2;
    int nc = out_size / 512;
    const int* src = ei;
    const int* dst = ei + E;

    float* X1;   cudaGetSymbolAddress((void**)&X1, g_X1);
    float* X2;   cudaGetSymbolAddress((void**)&X2, g_X2);
    float* X3;   cudaGetSymbolAddress((void**)&X3, g_X3);
    float* pool; cudaGetSymbolAddress((void**)&pool, g_pool);
    int *cnt, *off, *cur, *csr, *ccnt, *coff, *ccur, *ccsr;
    cudaGetSymbolAddress((void**)&cnt,  g_cnt);
    cudaGetSymbolAddress((void**)&off,  g_off);
    cudaGetSymbolAddress((void**)&cur,  g_cur);
    cudaGetSymbolAddress((void**)&csr,  g_csr);
    cudaGetSymbolAddress((void**)&ccnt, g_ccnt);
    cudaGetSymbolAddress((void**)&coff, g_coff);
    cudaGetSymbolAddress((void**)&ccur, g_ccur);
    cudaGetSymbolAddress((void**)&ccsr, g_ccsr);

    // Lazily-created side stream + events (created on the uncaptured
    // correctness call; reused identically on every call thereafter).
    static cudaStream_t s2 = nullptr;
    static cudaEvent_t evFork = nullptr, evCsr = nullptr;
    if (!s2) {
        cudaStreamCreateWithFlags(&s2, cudaStreamNonBlocking);
        cudaEventCreateWithFlags(&evFork, cudaEventDisableTiming);
        cudaEventCreateWithFlags(&evCsr,  cudaEventDisableTiming);
    }

    // ---- CSR build on side stream (overlaps mlp layer 0) ----
    cudaEventRecord(evFork, 0);
    cudaStreamWaitEvent(s2, evFork, 0);
    cudaMemsetAsync(cnt,  0, (size_t)n  * sizeof(int), s2);
    cudaMemsetAsync(ccnt, 0, (size_t)nc * sizeof(int), s2);
    hist_kernel<<<(E + 255) / 256, 256, 0, s2>>>(dst, cnt, E);
    hist_kernel<<<(n + 255) / 256, 256, 0, s2>>>(cl, ccnt, n);
    scan_kernel<<<1, 1024, 0, s2>>>(cnt, off, cur, n);
    scan_kernel<<<1, 1024, 0, s2>>>(ccnt, coff, ccur, nc);
    fill_edge_kernel<<<(E + 255) / 256, 256, 0, s2>>>(src, dst, cur, csr, E);
    fill_node_kernel<<<(n + 255) / 256, 256, 0, s2>>>(cl, ccur, ccsr, n);
    cudaEventRecord(evCsr, s2);

    int nb = (n + 63) / 64;

    // ---- Layer 0: C=64 ----
    mlp_kernel<64><<<nb, 256>>>(x, w1_0, b1_0, w2_0, b2_0, X1, n);
    cudaStreamWaitEvent(0, evCsr, 0);
    agg_kernel<64><<<((n + 1) / 2 * 32 + 255) / 256, 256>>>(X1, csr, off, n);

    // ---- Layer 1: C=128 ----
    mlp_kernel<128><<<nb, 256>>>(X1, w1_1, b1_1, w2_1, b2_1, X2, n);
    agg_kernel<128><<<(n * 32 + 255) / 256, 256>>>(X2, csr, off, n);

    // ---- Layer 2: C=256 ----
    mlp_kernel<256><<<nb, 256>>>(X2, w1_2, b1_2, w2_2, b2_2, X3, n);
    agg_kernel<256><<<(n * 32 + 255) / 256, 256>>>(X3, csr, off, n);

    // ---- Cluster pool + normalize ----
    pool_kernel<<<nc, 128>>>(X3, ccsr, coff, pool);
    normalize_kernel<<<16, 256>>>(pool, (float*)d_out, nc);
}